// round 1
// baseline (speedup 1.0000x reference)
#include <cuda_runtime.h>
#include <cuda_bf16.h>
#include <cstdint>
#include <cstdio>

// ---------------------------------------------------------------------------
// Problem constants (fixed by reference)
// ---------------------------------------------------------------------------
static const int NU = 50000;
static const int NV = 50000;
static const int NE = 500000;
static const int D  = 256;    // input dim == H*C
static const int HC = 256;    // H*C
#define NEG_SLOPE 0.2f
#define EPS_F 1e-16f

// ---------------------------------------------------------------------------
// Static device scratch (no allocation allowed)
// ---------------------------------------------------------------------------
__device__ __align__(128) float g_hs [50000 * 256];
__device__ __align__(128) float g_nv0[50000 * 256];
__device__ __align__(128) float g_nu0[50000 * 256];
__device__ __align__(128) float g_nu1[50000 * 256];
__device__ __align__(128) float g_es [50000 * 4];
__device__ __align__(128) float g_ed [50000 * 4];
__device__ __align__(128) float g_vd [256 * 4];
__device__ __align__(128) int   g_rowptr_uv[50001];
__device__ __align__(128) int   g_rowptr_vu[50001];
__device__ __align__(128) int   g_csrc_uv[500000];
__device__ __align__(128) int   g_csrc_vu[500000];
__device__ __align__(128) int   g_cnt[50001];
__device__ __align__(128) int   g_bsums[64];

// ---------------------------------------------------------------------------
// SGEMM: C[M,N] = A[M,K] @ B[K,N] (+ bias). fp32, K multiple of 16, N mult 64.
// BM=128, BN=64, BK=16, thread tile 8x4, 256 threads.
// ---------------------------------------------------------------------------
#define GBM 128
#define GBN 64
#define GBK 16
#define GTM 8
#define GTN 4

__global__ __launch_bounds__(256)
void sgemm_kernel(const float* __restrict__ A, const float* __restrict__ B,
                  const float* __restrict__ bias, float* __restrict__ C,
                  int M, int N, int K) {
    __shared__ float As[GBK][GBM];   // 8 KB, transposed A tile
    __shared__ float Bs[GBK][GBN];   // 4 KB

    int tid = threadIdx.x;
    int tx = tid & 15;           // N direction (x4)
    int ty = tid >> 4;           // M direction (x8)
    int bm = blockIdx.y * GBM;
    int bn = blockIdx.x * GBN;

    int arow = tid >> 2;         // 0..63
    int acol = (tid & 3) * 4;    // 0,4,8,12
    int brow = tid >> 4;         // 0..15
    int bcol = (tid & 15) * 4;   // 0..60

    float acc[GTM][GTN];
    #pragma unroll
    for (int i = 0; i < GTM; i++)
        #pragma unroll
        for (int j = 0; j < GTN; j++) acc[i][j] = 0.f;

    for (int kb = 0; kb < K; kb += GBK) {
        #pragma unroll
        for (int r = 0; r < 2; r++) {
            int m = bm + arow + r * 64;
            float4 v = make_float4(0.f, 0.f, 0.f, 0.f);
            if (m < M) v = *(const float4*)&A[(size_t)m * K + kb + acol];
            As[acol + 0][arow + r * 64] = v.x;
            As[acol + 1][arow + r * 64] = v.y;
            As[acol + 2][arow + r * 64] = v.z;
            As[acol + 3][arow + r * 64] = v.w;
        }
        *(float4*)&Bs[brow][bcol] =
            *(const float4*)&B[(size_t)(kb + brow) * N + bn + bcol];
        __syncthreads();

        #pragma unroll
        for (int kk = 0; kk < GBK; kk++) {
            float a[GTM], b[GTN];
            #pragma unroll
            for (int i = 0; i < GTM; i++) a[i] = As[kk][ty * GTM + i];
            #pragma unroll
            for (int j = 0; j < GTN; j++) b[j] = Bs[kk][tx * GTN + j];
            #pragma unroll
            for (int i = 0; i < GTM; i++)
                #pragma unroll
                for (int j = 0; j < GTN; j++)
                    acc[i][j] = fmaf(a[i], b[j], acc[i][j]);
        }
        __syncthreads();
    }

    #pragma unroll
    for (int i = 0; i < GTM; i++) {
        int m = bm + ty * GTM + i;
        if (m >= M) continue;
        #pragma unroll
        for (int j = 0; j < GTN; j++) {
            int n = bn + tx * GTN + j;
            float v = acc[i][j];
            if (bias) v += bias[n];
            C[(size_t)m * N + n] = v;
        }
    }
}

// ---------------------------------------------------------------------------
// es[n,h] = sum_c hs[n,h*64+c] * att_s[h*64+c]   (warp per node)
// ---------------------------------------------------------------------------
__global__ __launch_bounds__(256)
void es_kernel(const float* __restrict__ hs, const float* __restrict__ att,
               float* __restrict__ es, int N) {
    int warp = (blockIdx.x * blockDim.x + threadIdx.x) >> 5;
    int lane = threadIdx.x & 31;
    if (warp >= N) return;
    int h = lane >> 3;
    const float4* row = (const float4*)&hs[(size_t)warp * 256 + lane * 8];
    float4 a0 = row[0], a1 = row[1];
    const float4* at = (const float4*)&att[lane * 8];
    float4 b0 = at[0], b1 = at[1];
    float p = a0.x * b0.x + a0.y * b0.y + a0.z * b0.z + a0.w * b0.w
            + a1.x * b1.x + a1.y * b1.y + a1.z * b1.z + a1.w * b1.w;
    p += __shfl_xor_sync(0xffffffff, p, 4);
    p += __shfl_xor_sync(0xffffffff, p, 2);
    p += __shfl_xor_sync(0xffffffff, p, 1);
    if ((lane & 7) == 0) es[warp * 4 + h] = p;
}

// ---------------------------------------------------------------------------
// vd[k,h] = sum_c Wd[k,h*64+c] * att_d[h*64+c]   (single block, 256 threads)
// ---------------------------------------------------------------------------
__global__ void vd_kernel(const float* __restrict__ Wd,
                          const float* __restrict__ attd,
                          float* __restrict__ vd) {
    int k = threadIdx.x;
    #pragma unroll
    for (int h = 0; h < 4; h++) {
        float s = 0.f;
        #pragma unroll 8
        for (int c = 0; c < 64; c++)
            s = fmaf(Wd[(size_t)k * 256 + h * 64 + c], attd[h * 64 + c], s);
        vd[k * 4 + h] = s;
    }
}

// ---------------------------------------------------------------------------
// ed[n,h] = sum_k x[n,k] * vd[k,h]   (warp per node)
// ---------------------------------------------------------------------------
__global__ __launch_bounds__(256)
void ed_kernel(const float* __restrict__ x, const float* __restrict__ vd,
               float* __restrict__ ed, int N) {
    __shared__ float svd[1024];
    for (int i = threadIdx.x; i < 1024; i += blockDim.x) svd[i] = vd[i];
    __syncthreads();
    int warp = (blockIdx.x * blockDim.x + threadIdx.x) >> 5;
    int lane = threadIdx.x & 31;
    if (warp >= N) return;
    const float4* row = (const float4*)&x[(size_t)warp * 256 + lane * 8];
    float4 a0 = row[0], a1 = row[1];
    float xr[8] = {a0.x, a0.y, a0.z, a0.w, a1.x, a1.y, a1.z, a1.w};
    float p[4] = {0.f, 0.f, 0.f, 0.f};
    #pragma unroll
    for (int j = 0; j < 8; j++) {
        int k = lane * 8 + j;
        #pragma unroll
        for (int h = 0; h < 4; h++) p[h] = fmaf(xr[j], svd[k * 4 + h], p[h]);
    }
    #pragma unroll
    for (int h = 0; h < 4; h++) {
        float v = p[h];
        v += __shfl_xor_sync(0xffffffff, v, 16);
        v += __shfl_xor_sync(0xffffffff, v, 8);
        v += __shfl_xor_sync(0xffffffff, v, 4);
        v += __shfl_xor_sync(0xffffffff, v, 2);
        v += __shfl_xor_sync(0xffffffff, v, 1);
        if (lane == 0) ed[warp * 4 + h] = v;
    }
}

// ---------------------------------------------------------------------------
// Aggregation: warp per destination node. Fused softmax + weighted gather
// + bias + relu.  out[d,c] = relu( sum_e w_e*hs[src_e,c] / (denom+EPS) + b[c] )
// ---------------------------------------------------------------------------
__global__ __launch_bounds__(256)
void agg_kernel(const float* __restrict__ hs, const float* __restrict__ es,
                const float* __restrict__ ed, const int* __restrict__ rowptr,
                const int* __restrict__ csrc, const float* __restrict__ bias,
                float* __restrict__ out, int Nd) {
    int warp = (blockIdx.x * blockDim.x + threadIdx.x) >> 5;
    int lane = threadIdx.x & 31;
    if (warp >= Nd) return;
    int h = lane >> 3;
    float edh = ed[warp * 4 + h];
    int beg = rowptr[warp], end = rowptr[warp + 1];
    float denom = 0.f;
    float acc[8] = {0.f, 0.f, 0.f, 0.f, 0.f, 0.f, 0.f, 0.f};
    for (int e = beg; e < end; e++) {
        int s = csrc[e];
        float a = es[s * 4 + h] + edh;
        a = (a > 0.f) ? a : a * NEG_SLOPE;
        float w = __expf(a);
        denom += w;
        const float4* row = (const float4*)&hs[(size_t)s * 256 + lane * 8];
        float4 v0 = row[0], v1 = row[1];
        acc[0] = fmaf(w, v0.x, acc[0]);
        acc[1] = fmaf(w, v0.y, acc[1]);
        acc[2] = fmaf(w, v0.z, acc[2]);
        acc[3] = fmaf(w, v0.w, acc[3]);
        acc[4] = fmaf(w, v1.x, acc[4]);
        acc[5] = fmaf(w, v1.y, acc[5]);
        acc[6] = fmaf(w, v1.z, acc[6]);
        acc[7] = fmaf(w, v1.w, acc[7]);
    }
    float inv = 1.f / (denom + EPS_F);
    const float4* bp = (const float4*)&bias[lane * 8];
    float4 b0 = bp[0], b1 = bp[1];
    float4 o0, o1;
    o0.x = fmaxf(acc[0] * inv + b0.x, 0.f);
    o0.y = fmaxf(acc[1] * inv + b0.y, 0.f);
    o0.z = fmaxf(acc[2] * inv + b0.z, 0.f);
    o0.w = fmaxf(acc[3] * inv + b0.w, 0.f);
    o1.x = fmaxf(acc[4] * inv + b1.x, 0.f);
    o1.y = fmaxf(acc[5] * inv + b1.y, 0.f);
    o1.z = fmaxf(acc[6] * inv + b1.z, 0.f);
    o1.w = fmaxf(acc[7] * inv + b1.w, 0.f);
    float4* op = (float4*)&out[(size_t)warp * 256 + lane * 8];
    op[0] = o0;
    op[1] = o1;
}

// ---------------------------------------------------------------------------
// CSR build: zero / count / 3-phase scan / fill
// ---------------------------------------------------------------------------
__global__ void zero_kernel(int* p, int n) {
    int i = blockIdx.x * blockDim.x + threadIdx.x;
    if (i < n) p[i] = 0;
}

__global__ void count_kernel(const int* __restrict__ dst, int* __restrict__ cnt,
                             int E) {
    int e = blockIdx.x * blockDim.x + threadIdx.x;
    if (e < E) atomicAdd(&cnt[dst[e]], 1);
}

__global__ __launch_bounds__(1024)
void scan1_kernel(const int* __restrict__ in, int* __restrict__ out,
                  int* __restrict__ bsums, int n) {
    __shared__ int sh[1024];
    int i = blockIdx.x * 1024 + threadIdx.x;
    int v = (i < n) ? in[i] : 0;
    sh[threadIdx.x] = v;
    __syncthreads();
    for (int off = 1; off < 1024; off <<= 1) {
        int t = (threadIdx.x >= off) ? sh[threadIdx.x - off] : 0;
        __syncthreads();
        sh[threadIdx.x] += t;
        __syncthreads();
    }
    if (i < n) out[i] = sh[threadIdx.x] - v;  // exclusive
    if (threadIdx.x == 1023) bsums[blockIdx.x] = sh[1023];
}

__global__ void scan2_kernel(int* bsums, int nb) {
    if (threadIdx.x == 0 && blockIdx.x == 0) {
        int run = 0;
        for (int i = 0; i < nb; i++) { int v = bsums[i]; bsums[i] = run; run += v; }
    }
}

__global__ void scan3_kernel(int* out, const int* __restrict__ bsums, int n,
                             int total) {
    int i = blockIdx.x * blockDim.x + threadIdx.x;
    if (i < n) out[i] += bsums[i >> 10];
    if (i == 0) out[n] = total;
}

__global__ void fill_kernel(const int* __restrict__ src,
                            const int* __restrict__ dst,
                            const int* __restrict__ rowptr,
                            int* __restrict__ cursor, int* __restrict__ csrc,
                            int E) {
    int e = blockIdx.x * blockDim.x + threadIdx.x;
    if (e < E) {
        int d = dst[e];
        int pos = atomicAdd(&cursor[d], 1);
        csrc[rowptr[d] + pos] = src[e];
    }
}

// ---------------------------------------------------------------------------
// Host orchestration
// ---------------------------------------------------------------------------
static inline void* sym(const void* s) {
    void* p = nullptr;
    cudaGetSymbolAddress(&p, s);
    return p;
}

static void build_csr(const int* src, const int* dst, int Nd, int* rowptr,
                      int* csrc, int* cnt, int* bsums) {
    int nb = (Nd + 1023) / 1024;
    zero_kernel<<<(Nd + 255) / 256, 256>>>(cnt, Nd);
    count_kernel<<<(NE + 255) / 256, 256>>>(dst, cnt, NE);
    scan1_kernel<<<nb, 1024>>>(cnt, rowptr, bsums, Nd);
    scan2_kernel<<<1, 32>>>(bsums, nb);
    scan3_kernel<<<(Nd + 255) / 256, 256>>>(rowptr, bsums, Nd, NE);
    zero_kernel<<<(Nd + 255) / 256, 256>>>(cnt, Nd);
    fill_kernel<<<(NE + 255) / 256, 256>>>(src, dst, rowptr, cnt, csrc, NE);
}

// one GAT conv: out = relu(GAT(x_s, x_d; params)), [Nd, 256]
static void gat(const float* x_s, const float* x_d, int Ns, int Nd,
                const float* Ws, const float* Wd, const float* att_s,
                const float* att_d, const float* bias, const int* rowptr,
                const int* csrc, float* hs, float* es, float* ed, float* vd,
                float* out) {
    dim3 ggrid(HC / GBN, (Ns + GBM - 1) / GBM);
    sgemm_kernel<<<ggrid, 256>>>(x_s, Ws, nullptr, hs, Ns, HC, D);
    es_kernel<<<(Ns + 7) / 8, 256>>>(hs, att_s, es, Ns);
    vd_kernel<<<1, 256>>>(Wd, att_d, vd);
    ed_kernel<<<(Nd + 7) / 8, 256>>>(x_d, vd, ed, Nd);
    agg_kernel<<<(Nd + 7) / 8, 256>>>(hs, es, ed, rowptr, csrc, bias, out, Nd);
}

extern "C" void kernel_launch(void* const* d_in, const int* in_sizes, int n_in,
                              void* d_out, int out_size) {
    const float* x_u    = (const float*)d_in[0];
    const float* x_v    = (const float*)d_in[1];
    const float* W_src  = (const float*)d_in[2];   // [L,2,256,256]
    const float* W_dst  = (const float*)d_in[3];   // [L,2,256,256]
    const float* att_s  = (const float*)d_in[4];   // [L,2,4,64]
    const float* att_d  = (const float*)d_in[5];   // [L,2,4,64]
    const float* bias   = (const float*)d_in[6];   // [L,2,256]
    const float* lin_w  = (const float*)d_in[7];   // [256,128]
    const float* lin_b  = (const float*)d_in[8];   // [128]
    const int*   ei_uv  = (const int*)d_in[9];     // [2,E]: src(u), dst(v)
    const int*   ei_vu  = (const int*)d_in[10];    // [2,E]: src(v), dst(u)
    float* out = (float*)d_out;

    float* hs  = (float*)sym(g_hs);
    float* nv0 = (float*)sym(g_nv0);
    float* nu0 = (float*)sym(g_nu0);
    float* nu1 = (float*)sym(g_nu1);
    float* es  = (float*)sym(g_es);
    float* ed  = (float*)sym(g_ed);
    float* vd  = (float*)sym(g_vd);
    int* rp_uv = (int*)sym(g_rowptr_uv);
    int* rp_vu = (int*)sym(g_rowptr_vu);
    int* cs_uv = (int*)sym(g_csrc_uv);
    int* cs_vu = (int*)sym(g_csrc_vu);
    int* cnt   = (int*)sym(g_cnt);
    int* bsums = (int*)sym(g_bsums);

    // CSR by destination for both relations (reused across layers)
    build_csr(ei_uv, ei_uv + NE, NV, rp_uv, cs_uv, cnt, bsums);
    build_csr(ei_vu, ei_vu + NE, NU, rp_vu, cs_vu, cnt, bsums);

    const size_t WSZ = 256 * 256;  // one W slice
    const size_t ASZ = 4 * 64;     // one att slice
    const size_t BSZ = 256;        // one bias slice

    // layer 0, rel 0: u -> v   => nv0
    gat(x_u, x_v, NU, NV,
        W_src + 0 * WSZ, W_dst + 0 * WSZ, att_s + 0 * ASZ, att_d + 0 * ASZ,
        bias + 0 * BSZ, rp_uv, cs_uv, hs, es, ed, vd, nv0);
    // layer 0, rel 1: v -> u   => nu0
    gat(x_v, x_u, NV, NU,
        W_src + 1 * WSZ, W_dst + 1 * WSZ, att_s + 1 * ASZ, att_d + 1 * ASZ,
        bias + 1 * BSZ, rp_vu, cs_vu, hs, es, ed, vd, nu0);
    // layer 1, rel 1: v -> u with (x_v = nv0, x_u = nu0) => nu1
    // (layer-1 nv is dead: final output only depends on x_u)
    gat(nv0, nu0, NV, NU,
        W_src + 3 * WSZ, W_dst + 3 * WSZ, att_s + 3 * ASZ, att_d + 3 * ASZ,
        bias + 3 * BSZ, rp_vu, cs_vu, hs, es, ed, vd, nu1);

    // final linear: out = nu1 @ lin_w + lin_b   [50000,128]
    dim3 fgrid(128 / GBN, (NU + GBM - 1) / GBM);
    sgemm_kernel<<<fgrid, 256>>>(nu1, lin_w, lin_b, out, NU, 128, D);
}

// round 4
// speedup vs baseline: 1.4443x; 1.4443x over previous
#include <cuda_runtime.h>
#include <cuda_bf16.h>
#include <cstdint>

// ---------------------------------------------------------------------------
// Problem constants
// ---------------------------------------------------------------------------
static const int NU = 50000;
static const int NV = 50000;
static const int NE = 500000;
#define NEG_SLOPE 0.2f
#define EPS_F 1e-16f

// ---------------------------------------------------------------------------
// Static device scratch
// ---------------------------------------------------------------------------
__device__ __align__(128) float g_hs [50048 * 256];
__device__ __align__(128) float g_nv0[50048 * 256];
__device__ __align__(128) float g_nu0[50048 * 256];
__device__ __align__(128) float g_nu1[50048 * 256];
__device__ __align__(128) float g_es [50048 * 4];
__device__ __align__(128) float g_ed [50000 * 4];
__device__ __align__(128) float g_vd [256 * 4];
__device__ __align__(128) int   g_rowptr_uv[50001];
__device__ __align__(128) int   g_rowptr_vu[50001];
__device__ __align__(128) int   g_csrc_uv[500000];
__device__ __align__(128) int   g_csrc_vu[500000];
__device__ __align__(128) int   g_cnt[50001];
__device__ __align__(128) int   g_bsums[64];
// weights transposed to [N,K] bf16 hi/lo
__device__ __align__(128) __nv_bfloat16 g_wt_hi[3 * 256 * 256];
__device__ __align__(128) __nv_bfloat16 g_wt_lo[3 * 256 * 256];
__device__ __align__(128) __nv_bfloat16 g_lt_hi[128 * 256];
__device__ __align__(128) __nv_bfloat16 g_lt_lo[128 * 256];

// ---------------------------------------------------------------------------
// MMA helpers (baseline ISA: ldmatrix + mma.sync, sm_80+)
// ---------------------------------------------------------------------------
__device__ __forceinline__ uint32_t smem_u32(const void* p) {
    uint32_t a;
    asm("{ .reg .u64 t; cvta.to.shared.u64 t, %1; cvt.u32.u64 %0, t; }"
        : "=r"(a) : "l"(p));
    return a;
}

__device__ __forceinline__ void ldsm4(uint32_t& r0, uint32_t& r1, uint32_t& r2,
                                      uint32_t& r3, uint32_t addr) {
    asm volatile("ldmatrix.sync.aligned.m8n8.x4.shared.b16 {%0,%1,%2,%3}, [%4];"
                 : "=r"(r0), "=r"(r1), "=r"(r2), "=r"(r3) : "r"(addr));
}

__device__ __forceinline__ void mma_bf16(float* c, const uint32_t* a,
                                         const uint32_t* b) {
    asm volatile(
        "mma.sync.aligned.m16n8k16.row.col.f32.bf16.bf16.f32 "
        "{%0,%1,%2,%3}, {%4,%5,%6,%7}, {%8,%9}, {%0,%1,%2,%3};"
        : "+f"(c[0]), "+f"(c[1]), "+f"(c[2]), "+f"(c[3])
        : "r"(a[0]), "r"(a[1]), "r"(a[2]), "r"(a[3]), "r"(b[0]), "r"(b[1]));
}

// ---------------------------------------------------------------------------
// Weight transpose + bf16 split: Wt[n,k] = W[k,n] (hi/lo)
// ---------------------------------------------------------------------------
__global__ void wconv_kernel(const float* __restrict__ W, int N,
                             __nv_bfloat16* __restrict__ hi,
                             __nv_bfloat16* __restrict__ lo) {
    int n = blockIdx.x;
    int k = threadIdx.x;  // K = 256
    float f = W[(size_t)k * N + n];
    __nv_bfloat16 h = __float2bfloat16(f);
    hi[(size_t)n * 256 + k] = h;
    lo[(size_t)n * 256 + k] = __float2bfloat16(f - __bfloat162float(h));
}

// ---------------------------------------------------------------------------
// Tensor-core GEMM via mma.sync: C[M,N_] = A[M,256] @ Wt^T  (+bias)
// Wt is [N_,256] bf16 hi/lo.  2-term split: Ahi*Bhi + Ahi*Blo + Alo*Bhi.
// CTA tile 128x128, BK=32, 8 warps (2x4), warp tile 64x32.
// Register-prefetch pipeline: LDG chunk k+1 overlaps MMA on chunk k.
// ---------------------------------------------------------------------------
#define SKA 40   // padded SMEM k-stride (bf16 elems): 80B rows, ldmatrix conflict-free

template<int N_, bool BIAS>
__global__ __launch_bounds__(256)
void mma_gemm_kernel(const float* __restrict__ A,
                     const __nv_bfloat16* __restrict__ Bt_hi,
                     const __nv_bfloat16* __restrict__ Bt_lo,
                     const float* __restrict__ bias,
                     float* __restrict__ C, int M) {
    __shared__ __align__(16) __nv_bfloat16 As_hi[128][SKA];
    __shared__ __align__(16) __nv_bfloat16 As_lo[128][SKA];
    __shared__ __align__(16) __nv_bfloat16 Bs_hi[128][SKA];
    __shared__ __align__(16) __nv_bfloat16 Bs_lo[128][SKA];

    const int tid  = threadIdx.x;
    const int lane = tid & 31;
    const int wid  = tid >> 5;
    const int wm   = wid >> 2;       // 0-1  (M dir, 64 rows each)
    const int wn   = wid & 3;        // 0-3  (N dir, 32 cols each)
    const int bm   = blockIdx.x * 128;
    const int bn   = blockIdx.y * 128;

    // ldmatrix base addresses (per mtile / ntile-pair), +ks*32B for kstep 1
    uint32_t aBaseH[4], aBaseL[4], bBaseH[2], bBaseL[2];
    {
        int ar = wm * 64 + (lane & 15);
        int ac = (lane >> 4) * 8;
        #pragma unroll
        for (int i = 0; i < 4; i++) {
            aBaseH[i] = smem_u32(&As_hi[ar + i * 16][ac]);
            aBaseL[i] = smem_u32(&As_lo[ar + i * 16][ac]);
        }
        int br = wn * 32 + ((lane >> 4) << 3) + (lane & 7);
        int bc = ((lane >> 3) & 1) * 8;
        #pragma unroll
        for (int p = 0; p < 2; p++) {
            bBaseH[p] = smem_u32(&Bs_hi[br + p * 16][bc]);
            bBaseL[p] = smem_u32(&Bs_lo[br + p * 16][bc]);
        }
    }

    float acc[4][4][4];
    #pragma unroll
    for (int i = 0; i < 4; i++)
        #pragma unroll
        for (int j = 0; j < 4; j++)
            #pragma unroll
            for (int q = 0; q < 4; q++) acc[i][j][q] = 0.f;

    // staging registers
    float4 aS[4];
    uint4  bSh[2], bSl[2];

    auto stage_load = [&](int kc) {
        #pragma unroll
        for (int t = 0; t < 4; t++) {
            int idx = t * 256 + tid;
            int row = idx >> 3, c4 = idx & 7;
            aS[t] = make_float4(0.f, 0.f, 0.f, 0.f);
            if (bm + row < M)
                aS[t] = *(const float4*)&A[(size_t)(bm + row) * 256 + kc * 32 + c4 * 4];
        }
        #pragma unroll
        for (int t = 0; t < 2; t++) {
            int idx = t * 256 + tid;
            int row = idx >> 2, g = idx & 3;
            size_t go = (size_t)(bn + row) * 256 + kc * 32 + g * 8;
            bSh[t] = *(const uint4*)&Bt_hi[go];
            bSl[t] = *(const uint4*)&Bt_lo[go];
        }
    };

    stage_load(0);

    for (int kc = 0; kc < 8; kc++) {
        // ---- STS with fp32 -> bf16 hi/lo split ----
        #pragma unroll
        for (int t = 0; t < 4; t++) {
            int idx = t * 256 + tid;
            int row = idx >> 3, c4 = idx & 7;
            float4 v = aS[t];
            __nv_bfloat16 hx = __float2bfloat16(v.x), hy = __float2bfloat16(v.y);
            __nv_bfloat16 hz = __float2bfloat16(v.z), hw = __float2bfloat16(v.w);
            __nv_bfloat162 h0(hx, hy), h1(hz, hw);
            __nv_bfloat162 l0(__float2bfloat16(v.x - __bfloat162float(hx)),
                              __float2bfloat16(v.y - __bfloat162float(hy)));
            __nv_bfloat162 l1(__float2bfloat16(v.z - __bfloat162float(hz)),
                              __float2bfloat16(v.w - __bfloat162float(hw)));
            *(uint2*)&As_hi[row][c4 * 4] =
                make_uint2(*(uint32_t*)&h0, *(uint32_t*)&h1);
            *(uint2*)&As_lo[row][c4 * 4] =
                make_uint2(*(uint32_t*)&l0, *(uint32_t*)&l1);
        }
        #pragma unroll
        for (int t = 0; t < 2; t++) {
            int idx = t * 256 + tid;
            int row = idx >> 2, g = idx & 3;
            *(uint4*)&Bs_hi[row][g * 8] = bSh[t];
            *(uint4*)&Bs_lo[row][g * 8] = bSl[t];
        }
        __syncthreads();

        if (kc < 7) stage_load(kc + 1);   // overlap next LDG with MMAs

        #pragma unroll
        for (int ks = 0; ks < 2; ks++) {
            uint32_t ah[4][4], al[4][4], bh[4][2], bl[4][2];
            #pragma unroll
            for (int i = 0; i < 4; i++) {
                ldsm4(ah[i][0], ah[i][1], ah[i][2], ah[i][3], aBaseH[i] + ks * 32);
                ldsm4(al[i][0], al[i][1], al[i][2], al[i][3], aBaseL[i] + ks * 32);
            }
            #pragma unroll
            for (int p = 0; p < 2; p++) {
                uint32_t r0, r1, r2, r3;
                ldsm4(r0, r1, r2, r3, bBaseH[p] + ks * 32);
                bh[p * 2][0] = r0; bh[p * 2][1] = r1;
                bh[p * 2 + 1][0] = r2; bh[p * 2 + 1][1] = r3;
                ldsm4(r0, r1, r2, r3, bBaseL[p] + ks * 32);
                bl[p * 2][0] = r0; bl[p * 2][1] = r1;
                bl[p * 2 + 1][0] = r2; bl[p * 2 + 1][1] = r3;
            }
            #pragma unroll
            for (int i = 0; i < 4; i++)
                #pragma unroll
                for (int j = 0; j < 4; j++) {
                    mma_bf16(acc[i][j], ah[i], bh[j]);
                    mma_bf16(acc[i][j], ah[i], bl[j]);
                    mma_bf16(acc[i][j], al[i], bh[j]);
                }
        }
        __syncthreads();
    }

    // ---- epilogue ----
    #pragma unroll
    for (int i = 0; i < 4; i++) {
        int r0 = bm + wm * 64 + i * 16 + (lane >> 2);
        #pragma unroll
        for (int j = 0; j < 4; j++) {
            int cc = bn + wn * 32 + j * 8 + 2 * (lane & 3);
            float b0 = 0.f, b1 = 0.f;
            if (BIAS) { b0 = __ldg(&bias[cc]); b1 = __ldg(&bias[cc + 1]); }
            if (r0 < M)
                *(float2*)&C[(size_t)r0 * N_ + cc] =
                    make_float2(acc[i][j][0] + b0, acc[i][j][1] + b1);
            if (r0 + 8 < M)
                *(float2*)&C[(size_t)(r0 + 8) * N_ + cc] =
                    make_float2(acc[i][j][2] + b0, acc[i][j][3] + b1);
        }
    }
}

// ---------------------------------------------------------------------------
// es[n,h] = sum_c hs[n,h*64+c] * att_s[h*64+c]   (warp per node)
// ---------------------------------------------------------------------------
__global__ __launch_bounds__(256)
void es_kernel(const float* __restrict__ hs, const float* __restrict__ att,
               float* __restrict__ es, int N) {
    int warp = (blockIdx.x * blockDim.x + threadIdx.x) >> 5;
    int lane = threadIdx.x & 31;
    if (warp >= N) return;
    int h = lane >> 3;
    const float4* row = (const float4*)&hs[(size_t)warp * 256 + lane * 8];
    float4 a0 = row[0], a1 = row[1];
    const float4* at = (const float4*)&att[lane * 8];
    float4 b0 = at[0], b1 = at[1];
    float p = a0.x * b0.x + a0.y * b0.y + a0.z * b0.z + a0.w * b0.w
            + a1.x * b1.x + a1.y * b1.y + a1.z * b1.z + a1.w * b1.w;
    p += __shfl_xor_sync(0xffffffff, p, 4);
    p += __shfl_xor_sync(0xffffffff, p, 2);
    p += __shfl_xor_sync(0xffffffff, p, 1);
    if ((lane & 7) == 0) es[warp * 4 + h] = p;
}

// ---------------------------------------------------------------------------
// vd[k,h] = sum_c Wd[k,h*64+c] * att_d[h*64+c]
// ---------------------------------------------------------------------------
__global__ void vd_kernel(const float* __restrict__ Wd,
                          const float* __restrict__ attd,
                          float* __restrict__ vd) {
    int k = threadIdx.x;
    #pragma unroll
    for (int h = 0; h < 4; h++) {
        float s = 0.f;
        #pragma unroll 8
        for (int c = 0; c < 64; c++)
            s = fmaf(Wd[(size_t)k * 256 + h * 64 + c], attd[h * 64 + c], s);
        vd[k * 4 + h] = s;
    }
}

// ---------------------------------------------------------------------------
// ed[n,h] = sum_k x[n,k] * vd[k,h]   (warp per node)
// ---------------------------------------------------------------------------
__global__ __launch_bounds__(256)
void ed_kernel(const float* __restrict__ x, const float* __restrict__ vd,
               float* __restrict__ ed, int N) {
    __shared__ float svd[1024];
    for (int i = threadIdx.x; i < 1024; i += blockDim.x) svd[i] = vd[i];
    __syncthreads();
    int warp = (blockIdx.x * blockDim.x + threadIdx.x) >> 5;
    int lane = threadIdx.x & 31;
    if (warp >= N) return;
    const float4* row = (const float4*)&x[(size_t)warp * 256 + lane * 8];
    float4 a0 = row[0], a1 = row[1];
    float xr[8] = {a0.x, a0.y, a0.z, a0.w, a1.x, a1.y, a1.z, a1.w};
    float p[4] = {0.f, 0.f, 0.f, 0.f};
    #pragma unroll
    for (int j = 0; j < 8; j++) {
        int k = lane * 8 + j;
        #pragma unroll
        for (int h = 0; h < 4; h++) p[h] = fmaf(xr[j], svd[k * 4 + h], p[h]);
    }
    #pragma unroll
    for (int h = 0; h < 4; h++) {
        float v = p[h];
        v += __shfl_xor_sync(0xffffffff, v, 16);
        v += __shfl_xor_sync(0xffffffff, v, 8);
        v += __shfl_xor_sync(0xffffffff, v, 4);
        v += __shfl_xor_sync(0xffffffff, v, 2);
        v += __shfl_xor_sync(0xffffffff, v, 1);
        if (lane == 0) ed[warp * 4 + h] = v;
    }
}

// ---------------------------------------------------------------------------
// Aggregation: warp per destination node (softmax + weighted gather + relu)
// ---------------------------------------------------------------------------
__global__ __launch_bounds__(256)
void agg_kernel(const float* __restrict__ hs, const float* __restrict__ es,
                const float* __restrict__ ed, const int* __restrict__ rowptr,
                const int* __restrict__ csrc, const float* __restrict__ bias,
                float* __restrict__ out, int Nd) {
    int warp = (blockIdx.x * blockDim.x + threadIdx.x) >> 5;
    int lane = threadIdx.x & 31;
    if (warp >= Nd) return;
    int h = lane >> 3;
    float edh = ed[warp * 4 + h];
    int beg = rowptr[warp], end = rowptr[warp + 1];
    float denom = 0.f;
    float acc[8] = {0.f, 0.f, 0.f, 0.f, 0.f, 0.f, 0.f, 0.f};
    for (int e = beg; e < end; e++) {
        int s = csrc[e];
        float a = es[s * 4 + h] + edh;
        a = (a > 0.f) ? a : a * NEG_SLOPE;
        float w = __expf(a);
        denom += w;
        const float4* row = (const float4*)&hs[(size_t)s * 256 + lane * 8];
        float4 v0 = row[0], v1 = row[1];
        acc[0] = fmaf(w, v0.x, acc[0]);
        acc[1] = fmaf(w, v0.y, acc[1]);
        acc[2] = fmaf(w, v0.z, acc[2]);
        acc[3] = fmaf(w, v0.w, acc[3]);
        acc[4] = fmaf(w, v1.x, acc[4]);
        acc[5] = fmaf(w, v1.y, acc[5]);
        acc[6] = fmaf(w, v1.z, acc[6]);
        acc[7] = fmaf(w, v1.w, acc[7]);
    }
    float inv = 1.f / (denom + EPS_F);
    const float4* bp = (const float4*)&bias[lane * 8];
    float4 b0 = bp[0], b1 = bp[1];
    float4 o0, o1;
    o0.x = fmaxf(acc[0] * inv + b0.x, 0.f);
    o0.y = fmaxf(acc[1] * inv + b0.y, 0.f);
    o0.z = fmaxf(acc[2] * inv + b0.z, 0.f);
    o0.w = fmaxf(acc[3] * inv + b0.w, 0.f);
    o1.x = fmaxf(acc[4] * inv + b1.x, 0.f);
    o1.y = fmaxf(acc[5] * inv + b1.y, 0.f);
    o1.z = fmaxf(acc[6] * inv + b1.z, 0.f);
    o1.w = fmaxf(acc[7] * inv + b1.w, 0.f);
    float4* op = (float4*)&out[(size_t)warp * 256 + lane * 8];
    op[0] = o0;
    op[1] = o1;
}

// ---------------------------------------------------------------------------
// CSR build
// ---------------------------------------------------------------------------
__global__ void zero_kernel(int* p, int n) {
    int i = blockIdx.x * blockDim.x + threadIdx.x;
    if (i < n) p[i] = 0;
}

__global__ void count_kernel(const int* __restrict__ dst, int* __restrict__ cnt,
                             int E) {
    int e = blockIdx.x * blockDim.x + threadIdx.x;
    if (e < E) atomicAdd(&cnt[dst[e]], 1);
}

__global__ __launch_bounds__(1024)
void scan1_kernel(const int* __restrict__ in, int* __restrict__ out,
                  int* __restrict__ bsums, int n) {
    __shared__ int sh[1024];
    int i = blockIdx.x * 1024 + threadIdx.x;
    int v = (i < n) ? in[i] : 0;
    sh[threadIdx.x] = v;
    __syncthreads();
    for (int off = 1; off < 1024; off <<= 1) {
        int t = (threadIdx.x >= off) ? sh[threadIdx.x - off] : 0;
        __syncthreads();
        sh[threadIdx.x] += t;
        __syncthreads();
    }
    if (i < n) out[i] = sh[threadIdx.x] - v;
    if (threadIdx.x == 1023) bsums[blockIdx.x] = sh[1023];
}

__global__ void scan2_kernel(int* bsums, int nb) {
    if (threadIdx.x == 0 && blockIdx.x == 0) {
        int run = 0;
        for (int i = 0; i < nb; i++) { int v = bsums[i]; bsums[i] = run; run += v; }
    }
}

__global__ void scan3_kernel(int* out, const int* __restrict__ bsums, int n,
                             int total) {
    int i = blockIdx.x * blockDim.x + threadIdx.x;
    if (i < n) out[i] += bsums[i >> 10];
    if (i == 0) out[n] = total;
}

__global__ void fill_kernel(const int* __restrict__ src,
                            const int* __restrict__ dst,
                            const int* __restrict__ rowptr,
                            int* __restrict__ cursor, int* __restrict__ csrc,
                            int E) {
    int e = blockIdx.x * blockDim.x + threadIdx.x;
    if (e < E) {
        int d = dst[e];
        int pos = atomicAdd(&cursor[d], 1);
        csrc[rowptr[d] + pos] = src[e];
    }
}

// ---------------------------------------------------------------------------
// Host orchestration
// ---------------------------------------------------------------------------
static inline void* sym(const void* s) {
    void* p = nullptr;
    cudaGetSymbolAddress(&p, s);
    return p;
}

static void build_csr(const int* src, const int* dst, int Nd, int* rowptr,
                      int* csrc, int* cnt, int* bsums) {
    int nb = (Nd + 1023) / 1024;
    zero_kernel<<<(Nd + 255) / 256, 256>>>(cnt, Nd);
    count_kernel<<<(NE + 255) / 256, 256>>>(dst, cnt, NE);
    scan1_kernel<<<nb, 1024>>>(cnt, rowptr, bsums, Nd);
    scan2_kernel<<<1, 32>>>(bsums, nb);
    scan3_kernel<<<(Nd + 255) / 256, 256>>>(rowptr, bsums, Nd, NE);
    zero_kernel<<<(Nd + 255) / 256, 256>>>(cnt, Nd);
    fill_kernel<<<(NE + 255) / 256, 256>>>(src, dst, rowptr, cnt, csrc, NE);
}

extern "C" void kernel_launch(void* const* d_in, const int* in_sizes, int n_in,
                              void* d_out, int out_size) {
    const float* x_u    = (const float*)d_in[0];
    const float* x_v    = (const float*)d_in[1];
    const float* W_src  = (const float*)d_in[2];   // [L,2,256,256]
    const float* W_dst  = (const float*)d_in[3];   // [L,2,256,256]
    const float* att_s  = (const float*)d_in[4];   // [L,2,4,64]
    const float* att_d  = (const float*)d_in[5];
    const float* bias   = (const float*)d_in[6];   // [L,2,256]
    const float* lin_w  = (const float*)d_in[7];   // [256,128]
    const float* lin_b  = (const float*)d_in[8];   // [128]
    const int*   ei_uv  = (const int*)d_in[9];
    const int*   ei_vu  = (const int*)d_in[10];
    float* out = (float*)d_out;

    float* hs  = (float*)sym(g_hs);
    float* nv0 = (float*)sym(g_nv0);
    float* nu0 = (float*)sym(g_nu0);
    float* nu1 = (float*)sym(g_nu1);
    float* es  = (float*)sym(g_es);
    float* ed  = (float*)sym(g_ed);
    float* vd  = (float*)sym(g_vd);
    int* rp_uv = (int*)sym(g_rowptr_uv);
    int* rp_vu = (int*)sym(g_rowptr_vu);
    int* cs_uv = (int*)sym(g_csrc_uv);
    int* cs_vu = (int*)sym(g_csrc_vu);
    int* cnt   = (int*)sym(g_cnt);
    int* bsums = (int*)sym(g_bsums);
    __nv_bfloat16* wt_hi = (__nv_bfloat16*)sym(g_wt_hi);
    __nv_bfloat16* wt_lo = (__nv_bfloat16*)sym(g_wt_lo);
    __nv_bfloat16* lt_hi = (__nv_bfloat16*)sym(g_lt_hi);
    __nv_bfloat16* lt_lo = (__nv_bfloat16*)sym(g_lt_lo);

    const size_t WSZ = 256 * 256;
    const size_t ASZ = 4 * 64;
    const size_t BSZ = 256;
    const int MT = (NU + 127) / 128;      // 391
    const dim3 g256(MT, 2), g128(MT, 1);

    // weight conversions (W_src slices 0,1,3; lin_w)
    wconv_kernel<<<256, 256>>>(W_src + 0 * WSZ, 256, wt_hi + 0 * WSZ, wt_lo + 0 * WSZ);
    wconv_kernel<<<256, 256>>>(W_src + 1 * WSZ, 256, wt_hi + 1 * WSZ, wt_lo + 1 * WSZ);
    wconv_kernel<<<256, 256>>>(W_src + 3 * WSZ, 256, wt_hi + 2 * WSZ, wt_lo + 2 * WSZ);
    wconv_kernel<<<128, 256>>>(lin_w, 128, lt_hi, lt_lo);

    // CSR by destination (shared by both layers)
    build_csr(ei_uv, ei_uv + NE, NV, rp_uv, cs_uv, cnt, bsums);
    build_csr(ei_vu, ei_vu + NE, NU, rp_vu, cs_vu, cnt, bsums);

    // gat0: u -> v  => nv0
    mma_gemm_kernel<256, false><<<g256, 256>>>(x_u, wt_hi + 0 * WSZ, wt_lo + 0 * WSZ,
                                               nullptr, hs, NU);
    es_kernel<<<(NU + 7) / 8, 256>>>(hs, att_s + 0 * ASZ, es, NU);
    vd_kernel<<<1, 256>>>(W_dst + 0 * WSZ, att_d + 0 * ASZ, vd);
    ed_kernel<<<(NV + 7) / 8, 256>>>(x_v, vd, ed, NV);
    agg_kernel<<<(NV + 7) / 8, 256>>>(hs, es, ed, rp_uv, cs_uv, bias + 0 * BSZ, nv0, NV);

    // gat1: v -> u  => nu0
    mma_gemm_kernel<256, false><<<g256, 256>>>(x_v, wt_hi + 1 * WSZ, wt_lo + 1 * WSZ,
                                               nullptr, hs, NV);
    es_kernel<<<(NV + 7) / 8, 256>>>(hs, att_s + 1 * ASZ, es, NV);
    vd_kernel<<<1, 256>>>(W_dst + 1 * WSZ, att_d + 1 * ASZ, vd);
    ed_kernel<<<(NU + 7) / 8, 256>>>(x_u, vd, ed, NU);
    agg_kernel<<<(NU + 7) / 8, 256>>>(hs, es, ed, rp_vu, cs_vu, bias + 1 * BSZ, nu0, NU);

    // gat2 (layer1, rel1): v -> u with x_v=nv0, x_u=nu0  => nu1
    mma_gemm_kernel<256, false><<<g256, 256>>>(nv0, wt_hi + 2 * WSZ, wt_lo + 2 * WSZ,
                                               nullptr, hs, NV);
    es_kernel<<<(NV + 7) / 8, 256>>>(hs, att_s + 3 * ASZ, es, NV);
    vd_kernel<<<1, 256>>>(W_dst + 3 * WSZ, att_d + 3 * ASZ, vd);
    ed_kernel<<<(NU + 7) / 8, 256>>>(nu0, vd, ed, NU);
    agg_kernel<<<(NU + 7) / 8, 256>>>(hs, es, ed, rp_vu, cs_vu, bias + 3 * BSZ, nu1, NU);

    // final linear: out = nu1 @ lin_w + lin_b   [50000,128]
    mma_gemm_kernel<128, true><<<g128, 256>>>(nu1, lt_hi, lt_lo, lin_b, out, NU);
}

// round 5
// speedup vs baseline: 1.7139x; 1.1867x over previous
#include <cuda_runtime.h>
#include <cuda_bf16.h>
#include <cstdint>

typedef __nv_bfloat16 bf16;

static const int NU = 50000;
static const int NV = 50000;
static const int NE = 500000;
#define NEG_SLOPE 0.2f
#define EPS_F 1e-16f

// ---------------------------------------------------------------------------
// Static device scratch
// ---------------------------------------------------------------------------
__device__ __align__(128) float g_hs[50048 * 256];
__device__ __align__(128) bf16 g_xu_hi[50048 * 256], g_xu_lo[50048 * 256];
__device__ __align__(128) bf16 g_xv_hi[50048 * 256], g_xv_lo[50048 * 256];
__device__ __align__(128) bf16 g_nv0_hi[50048 * 256], g_nv0_lo[50048 * 256];
__device__ __align__(128) bf16 g_nu0_hi[50048 * 256], g_nu0_lo[50048 * 256];
__device__ __align__(128) bf16 g_nu1_hi[50048 * 256], g_nu1_lo[50048 * 256];
__device__ __align__(128) float g_es0[50048 * 4], g_es1[50048 * 4], g_es2[50048 * 4];
__device__ __align__(128) float g_ed0[50048 * 4], g_ed1[50048 * 4], g_ed2[50048 * 4];
__device__ __align__(128) float g_cmbT_u[8 * 256], g_cmbT_v[8 * 256];
__device__ __align__(128) float g_wsatt2T[4 * 256], g_vd2T[4 * 256];
__device__ __align__(128) bf16 g_wt_hi[3 * 256 * 256], g_wt_lo[3 * 256 * 256];
__device__ __align__(128) bf16 g_lt_hi[128 * 256], g_lt_lo[128 * 256];
__device__ __align__(128) int g_rowptr_uv[50001], g_rowptr_vu[50001];
__device__ __align__(128) int g_csrc_uv[500000], g_csrc_vu[500000];
__device__ __align__(128) int g_cnt[50001], g_bsums[64];

// ---------------------------------------------------------------------------
// helpers
// ---------------------------------------------------------------------------
__device__ __forceinline__ uint32_t smem_u32(const void* p) {
    uint32_t a;
    asm("{ .reg .u64 t; cvta.to.shared.u64 t, %1; cvt.u32.u64 %0, t; }"
        : "=r"(a) : "l"(p));
    return a;
}

__device__ __forceinline__ void cp16(uint32_t dst, const void* src) {
    asm volatile("cp.async.cg.shared.global [%0], [%1], 16;"
                 :: "r"(dst), "l"(src));
}

__device__ __forceinline__ void ldsm4(uint32_t& r0, uint32_t& r1, uint32_t& r2,
                                      uint32_t& r3, uint32_t addr) {
    asm volatile("ldmatrix.sync.aligned.m8n8.x4.shared.b16 {%0,%1,%2,%3}, [%4];"
                 : "=r"(r0), "=r"(r1), "=r"(r2), "=r"(r3) : "r"(addr));
}

__device__ __forceinline__ void mma_bf16(float* c, const uint32_t* a,
                                         const uint32_t* b) {
    asm volatile(
        "mma.sync.aligned.m16n8k16.row.col.f32.bf16.bf16.f32 "
        "{%0,%1,%2,%3}, {%4,%5,%6,%7}, {%8,%9}, {%0,%1,%2,%3};"
        : "+f"(c[0]), "+f"(c[1]), "+f"(c[2]), "+f"(c[3])
        : "r"(a[0]), "r"(a[1]), "r"(a[2]), "r"(a[3]), "r"(b[0]), "r"(b[1]));
}

// ---------------------------------------------------------------------------
// wconv_all: transpose+split 3 W_src slices + lin_w in ONE launch
// ---------------------------------------------------------------------------
__global__ void wconv_all(const float* __restrict__ W_src,
                          const float* __restrict__ lin_w,
                          bf16* __restrict__ wt_hi, bf16* __restrict__ wt_lo,
                          bf16* __restrict__ lt_hi, bf16* __restrict__ lt_lo) {
    int b = blockIdx.x, k = threadIdx.x;
    if (b < 768) {
        int sl = b >> 8, n = b & 255;
        const float* W = W_src + (size_t)(sl == 2 ? 3 : sl) * 65536;
        float f = W[(size_t)k * 256 + n];
        bf16 h = __float2bfloat16(f);
        wt_hi[((size_t)sl * 256 + n) * 256 + k] = h;
        wt_lo[((size_t)sl * 256 + n) * 256 + k] =
            __float2bfloat16(f - __bfloat162float(h));
    } else {
        int n = b - 768;
        float f = lin_w[(size_t)k * 128 + n];
        bf16 h = __float2bfloat16(f);
        lt_hi[(size_t)n * 256 + k] = h;
        lt_lo[(size_t)n * 256 + k] = __float2bfloat16(f - __bfloat162float(h));
    }
}

// ---------------------------------------------------------------------------
// xsplit: fp32 -> bf16 hi/lo
// ---------------------------------------------------------------------------
__global__ __launch_bounds__(256)
void xsplit_kernel(const float* __restrict__ x, bf16* __restrict__ hi,
                   bf16* __restrict__ lo, int n4) {
    int i = blockIdx.x * blockDim.x + threadIdx.x;
    if (i >= n4) return;
    float4 v = ((const float4*)x)[i];
    bf16 hx = __float2bfloat16(v.x), hy = __float2bfloat16(v.y);
    bf16 hz = __float2bfloat16(v.z), hw = __float2bfloat16(v.w);
    __nv_bfloat162 h0(hx, hy), h1(hz, hw);
    __nv_bfloat162 l0(__float2bfloat16(v.x - __bfloat162float(hx)),
                      __float2bfloat16(v.y - __bfloat162float(hy)));
    __nv_bfloat162 l1(__float2bfloat16(v.z - __bfloat162float(hz)),
                      __float2bfloat16(v.w - __bfloat162float(hw)));
    ((uint2*)hi)[i] = make_uint2(*(uint32_t*)&h0, *(uint32_t*)&h1);
    ((uint2*)lo)[i] = make_uint2(*(uint32_t*)&l0, *(uint32_t*)&l1);
}

// ---------------------------------------------------------------------------
// prep_smat_all: tiny attention-projection matrices, transposed [h][k]
// block0: cmbT_u (wsatt0 | vd1)   block1: cmbT_v (wsatt1 | vd0)
// block2: wsatt2T                 block3: vd2T
// ---------------------------------------------------------------------------
__global__ void prep_smat_all(const float* __restrict__ Ws,
                              const float* __restrict__ Wd,
                              const float* __restrict__ as_,
                              const float* __restrict__ ad_,
                              float* __restrict__ cmbT_u,
                              float* __restrict__ cmbT_v,
                              float* __restrict__ wsatt2T,
                              float* __restrict__ vd2T) {
    int k = threadIdx.x, b = blockIdx.x;
    auto dot = [&](const float* W, const float* a, int h) {
        float s = 0.f;
        #pragma unroll 8
        for (int c = 0; c < 64; c++)
            s = fmaf(W[(size_t)k * 256 + h * 64 + c], a[h * 64 + c], s);
        return s;
    };
    if (b == 0) {
        for (int h = 0; h < 4; h++) cmbT_u[h * 256 + k] = dot(Ws, as_, h);
        for (int h = 0; h < 4; h++)
            cmbT_u[(4 + h) * 256 + k] = dot(Wd + 65536, ad_ + 256, h);
    } else if (b == 1) {
        for (int h = 0; h < 4; h++)
            cmbT_v[h * 256 + k] = dot(Ws + 65536, as_ + 256, h);
        for (int h = 0; h < 4; h++) cmbT_v[(4 + h) * 256 + k] = dot(Wd, ad_, h);
    } else if (b == 2) {
        for (int h = 0; h < 4; h++)
            wsatt2T[h * 256 + k] = dot(Ws + 3 * 65536, as_ + 3 * 256, h);
    } else {
        for (int h = 0; h < 4; h++)
            vd2T[h * 256 + k] = dot(Wd + 3 * 65536, ad_ + 3 * 256, h);
    }
}

// ---------------------------------------------------------------------------
// smallmat: [N,8] = x @ cmbT^T ; cols 0-3 -> es, cols 4-7 -> ed. Warp/node.
// ---------------------------------------------------------------------------
__global__ __launch_bounds__(256)
void smallmat_kernel(const float* __restrict__ x, const float* __restrict__ cmbT,
                     float* __restrict__ es, float* __restrict__ ed, int N) {
    __shared__ float sT[8 * 256];
    for (int i = threadIdx.x; i < 2048; i += 256) sT[i] = cmbT[i];
    __syncthreads();
    int warp = (blockIdx.x * blockDim.x + threadIdx.x) >> 5;
    int lane = threadIdx.x & 31;
    if (warp >= N) return;
    const float4* row = (const float4*)&x[(size_t)warp * 256 + lane * 8];
    float4 a0 = row[0], a1 = row[1];
    const float4* sT4 = (const float4*)sT;
    float p[8];
    #pragma unroll
    for (int h = 0; h < 8; h++) {
        float4 c0 = sT4[h * 64 + lane * 2], c1 = sT4[h * 64 + lane * 2 + 1];
        p[h] = a0.x * c0.x + a0.y * c0.y + a0.z * c0.z + a0.w * c0.w
             + a1.x * c1.x + a1.y * c1.y + a1.z * c1.z + a1.w * c1.w;
    }
    #pragma unroll
    for (int h = 0; h < 8; h++) {
        p[h] += __shfl_xor_sync(0xffffffff, p[h], 16);
        p[h] += __shfl_xor_sync(0xffffffff, p[h], 8);
        p[h] += __shfl_xor_sync(0xffffffff, p[h], 4);
        p[h] += __shfl_xor_sync(0xffffffff, p[h], 2);
        p[h] += __shfl_xor_sync(0xffffffff, p[h], 1);
    }
    if (lane == 0) {
        ((float4*)es)[warp] = make_float4(p[0], p[1], p[2], p[3]);
        ((float4*)ed)[warp] = make_float4(p[4], p[5], p[6], p[7]);
    }
}

// ---------------------------------------------------------------------------
// GEMM: C[M,NSTR] = (Ahi+Alo) @ (Bhi+Blo)^T, bf16 split, cp.async 2-stage.
// CTA 128x128, BK=32, 8 warps (2x4), warp tile 64x32.
// SMEM: 2 bufs x 4 arrays x [128][40] bf16 = 80 KB dynamic.
// ---------------------------------------------------------------------------
#define GSMEM 81920

template<int NSTR, bool BIAS>
__global__ __launch_bounds__(256)
void mma_gemm_bf16(const bf16* __restrict__ Ahi, const bf16* __restrict__ Alo,
                   const bf16* __restrict__ Bhi, const bf16* __restrict__ Blo,
                   const float* __restrict__ bias, float* __restrict__ C, int M) {
    extern __shared__ __align__(128) char smg[];
    const uint32_t sb = smem_u32(smg);
    const int tid = threadIdx.x, lane = tid & 31, wid = tid >> 5;
    const int wm = wid >> 2, wn = wid & 3;
    const int bm = blockIdx.x * 128, bn = blockIdx.y * 128;

    const char* src[4] = {
        (const char*)(Ahi + (size_t)bm * 256), (const char*)(Alo + (size_t)bm * 256),
        (const char*)(Bhi + (size_t)bn * 256), (const char*)(Blo + (size_t)bn * 256)};

    uint32_t aBH[4], aBL[4], bBH[2], bBL[2];
    {
        int ar = wm * 64 + (lane & 15), ac = (lane >> 4) * 8;
        #pragma unroll
        for (int i = 0; i < 4; i++) {
            aBH[i] = sb + (uint32_t)(ar + i * 16) * 80 + ac * 2;
            aBL[i] = aBH[i] + 10240;
        }
        int br = wn * 32 + ((lane >> 4) << 3) + (lane & 7);
        int bc = ((lane >> 3) & 1) * 8;
        #pragma unroll
        for (int p = 0; p < 2; p++) {
            bBH[p] = sb + 20480 + (uint32_t)(br + p * 16) * 80 + bc * 2;
            bBL[p] = bBH[p] + 10240;
        }
    }

    float acc[4][4][4];
    #pragma unroll
    for (int i = 0; i < 4; i++)
        #pragma unroll
        for (int j = 0; j < 4; j++)
            #pragma unroll
            for (int q = 0; q < 4; q++) acc[i][j][q] = 0.f;

    auto load_stage = [&](int kc, int buf) {
        #pragma unroll
        for (int arr = 0; arr < 4; arr++) {
            const char* s = src[arr] + kc * 64;
            uint32_t d = sb + buf * 40960 + arr * 10240;
            #pragma unroll
            for (int t2 = 0; t2 < 2; t2++) {
                int cid = t2 * 256 + tid, row = cid >> 2, c = cid & 3;
                cp16(d + row * 80 + c * 16, s + (size_t)row * 512 + c * 16);
            }
        }
        asm volatile("cp.async.commit_group;");
    };

    load_stage(0, 0);
    for (int kc = 0; kc < 8; kc++) {
        int buf = kc & 1;
        if (kc < 7) {
            load_stage(kc + 1, buf ^ 1);
            asm volatile("cp.async.wait_group 1;");
        } else {
            asm volatile("cp.async.wait_group 0;");
        }
        __syncthreads();
        uint32_t bo = (uint32_t)buf * 40960;
        #pragma unroll
        for (int ks = 0; ks < 2; ks++) {
            uint32_t ah[4][4], al[4][4], bh[4][2], bl[4][2];
            #pragma unroll
            for (int i = 0; i < 4; i++) {
                ldsm4(ah[i][0], ah[i][1], ah[i][2], ah[i][3], aBH[i] + bo + ks * 32);
                ldsm4(al[i][0], al[i][1], al[i][2], al[i][3], aBL[i] + bo + ks * 32);
            }
            #pragma unroll
            for (int p = 0; p < 2; p++) {
                uint32_t r0, r1, r2, r3;
                ldsm4(r0, r1, r2, r3, bBH[p] + bo + ks * 32);
                bh[p * 2][0] = r0; bh[p * 2][1] = r1;
                bh[p * 2 + 1][0] = r2; bh[p * 2 + 1][1] = r3;
                ldsm4(r0, r1, r2, r3, bBL[p] + bo + ks * 32);
                bl[p * 2][0] = r0; bl[p * 2][1] = r1;
                bl[p * 2 + 1][0] = r2; bl[p * 2 + 1][1] = r3;
            }
            #pragma unroll
            for (int i = 0; i < 4; i++)
                #pragma unroll
                for (int j = 0; j < 4; j++) {
                    mma_bf16(acc[i][j], ah[i], bh[j]);
                    mma_bf16(acc[i][j], ah[i], bl[j]);
                    mma_bf16(acc[i][j], al[i], bh[j]);
                }
        }
        __syncthreads();
    }

    #pragma unroll
    for (int i = 0; i < 4; i++) {
        int r0 = bm + wm * 64 + i * 16 + (lane >> 2);
        #pragma unroll
        for (int j = 0; j < 4; j++) {
            int cc = bn + wn * 32 + j * 8 + 2 * (lane & 3);
            float b0 = 0.f, b1 = 0.f;
            if (BIAS) { b0 = __ldg(&bias[cc]); b1 = __ldg(&bias[cc + 1]); }
            if (r0 < M)
                *(float2*)&C[(size_t)r0 * NSTR + cc] =
                    make_float2(acc[i][j][0] + b0, acc[i][j][1] + b1);
            if (r0 + 8 < M)
                *(float2*)&C[(size_t)(r0 + 8) * NSTR + cc] =
                    make_float2(acc[i][j][2] + b0, acc[i][j][3] + b1);
        }
    }
}

// ---------------------------------------------------------------------------
// Aggregation (warp/node): softmax + gather + bias + relu, bf16 hi/lo output.
// AUX=1: also compute auxout[n,h] = out_row . auxT[h] (layer-2 es/ed).
// ---------------------------------------------------------------------------
template<int AUX>
__global__ __launch_bounds__(256)
void agg_kernel(const float* __restrict__ hs, const float* __restrict__ es,
                const float* __restrict__ ed, const int* __restrict__ rowptr,
                const int* __restrict__ csrc, const float* __restrict__ bias,
                bf16* __restrict__ outhi, bf16* __restrict__ outlo,
                const float* __restrict__ auxT, float* __restrict__ auxout,
                int Nd) {
    __shared__ float saux[1024];
    if (AUX) {
        for (int i = threadIdx.x; i < 1024; i += 256) saux[i] = auxT[i];
        __syncthreads();
    }
    int warp = (blockIdx.x * blockDim.x + threadIdx.x) >> 5;
    int lane = threadIdx.x & 31;
    if (warp >= Nd) return;
    int h = lane >> 3;
    float edh = ed[warp * 4 + h];
    int beg = rowptr[warp], end = rowptr[warp + 1];
    float denom = 0.f;
    float acc[8] = {0.f, 0.f, 0.f, 0.f, 0.f, 0.f, 0.f, 0.f};
    for (int e = beg; e < end; e++) {
        int s = csrc[e];
        float a = es[s * 4 + h] + edh;
        a = (a > 0.f) ? a : a * NEG_SLOPE;
        float w = __expf(a);
        denom += w;
        const float4* row = (const float4*)&hs[(size_t)s * 256 + lane * 8];
        float4 v0 = row[0], v1 = row[1];
        acc[0] = fmaf(w, v0.x, acc[0]); acc[1] = fmaf(w, v0.y, acc[1]);
        acc[2] = fmaf(w, v0.z, acc[2]); acc[3] = fmaf(w, v0.w, acc[3]);
        acc[4] = fmaf(w, v1.x, acc[4]); acc[5] = fmaf(w, v1.y, acc[5]);
        acc[6] = fmaf(w, v1.z, acc[6]); acc[7] = fmaf(w, v1.w, acc[7]);
    }
    float inv = 1.f / (denom + EPS_F);
    const float4* bp = (const float4*)&bias[lane * 8];
    float4 b0 = bp[0], b1 = bp[1];
    float o[8];
    o[0] = fmaxf(acc[0] * inv + b0.x, 0.f);
    o[1] = fmaxf(acc[1] * inv + b0.y, 0.f);
    o[2] = fmaxf(acc[2] * inv + b0.z, 0.f);
    o[3] = fmaxf(acc[3] * inv + b0.w, 0.f);
    o[4] = fmaxf(acc[4] * inv + b1.x, 0.f);
    o[5] = fmaxf(acc[5] * inv + b1.y, 0.f);
    o[6] = fmaxf(acc[6] * inv + b1.z, 0.f);
    o[7] = fmaxf(acc[7] * inv + b1.w, 0.f);

    // write bf16 hi/lo
    uint32_t hw[4], lw[4];
    #pragma unroll
    for (int q = 0; q < 4; q++) {
        bf16 ha = __float2bfloat16(o[q * 2]), hb = __float2bfloat16(o[q * 2 + 1]);
        __nv_bfloat162 hp(ha, hb);
        __nv_bfloat162 lp(__float2bfloat16(o[q * 2] - __bfloat162float(ha)),
                          __float2bfloat16(o[q * 2 + 1] - __bfloat162float(hb)));
        hw[q] = *(uint32_t*)&hp;
        lw[q] = *(uint32_t*)&lp;
    }
    *(uint4*)&outhi[(size_t)warp * 256 + lane * 8] =
        make_uint4(hw[0], hw[1], hw[2], hw[3]);
    *(uint4*)&outlo[(size_t)warp * 256 + lane * 8] =
        make_uint4(lw[0], lw[1], lw[2], lw[3]);

    if (AUX) {
        const float4* sT4 = (const float4*)saux;
        float ph[4];
        #pragma unroll
        for (int hh = 0; hh < 4; hh++) {
            float4 c0 = sT4[hh * 64 + lane * 2], c1 = sT4[hh * 64 + lane * 2 + 1];
            float p = o[0] * c0.x + o[1] * c0.y + o[2] * c0.z + o[3] * c0.w
                    + o[4] * c1.x + o[5] * c1.y + o[6] * c1.z + o[7] * c1.w;
            p += __shfl_xor_sync(0xffffffff, p, 16);
            p += __shfl_xor_sync(0xffffffff, p, 8);
            p += __shfl_xor_sync(0xffffffff, p, 4);
            p += __shfl_xor_sync(0xffffffff, p, 2);
            p += __shfl_xor_sync(0xffffffff, p, 1);
            ph[hh] = p;
        }
        if (lane == 0)
            ((float4*)auxout)[warp] = make_float4(ph[0], ph[1], ph[2], ph[3]);
    }
}

// ---------------------------------------------------------------------------
// CSR build
// ---------------------------------------------------------------------------
__global__ void zero_kernel(int* p, int n) {
    int i = blockIdx.x * blockDim.x + threadIdx.x;
    if (i < n) p[i] = 0;
}

__global__ void count_kernel(const int* __restrict__ dst, int* __restrict__ cnt,
                             int E) {
    int e = blockIdx.x * blockDim.x + threadIdx.x;
    if (e < E) atomicAdd(&cnt[dst[e]], 1);
}

__global__ __launch_bounds__(1024)
void scan1_kernel(const int* __restrict__ in, int* __restrict__ out,
                  int* __restrict__ bsums, int n) {
    __shared__ int sh[1024];
    int i = blockIdx.x * 1024 + threadIdx.x;
    int v = (i < n) ? in[i] : 0;
    sh[threadIdx.x] = v;
    __syncthreads();
    for (int off = 1; off < 1024; off <<= 1) {
        int t = (threadIdx.x >= off) ? sh[threadIdx.x - off] : 0;
        __syncthreads();
        sh[threadIdx.x] += t;
        __syncthreads();
    }
    if (i < n) out[i] = sh[threadIdx.x] - v;
    if (threadIdx.x == 1023) bsums[blockIdx.x] = sh[1023];
}

__global__ void scan2_kernel(int* bsums, int nb) {
    if (threadIdx.x == 0 && blockIdx.x == 0) {
        int run = 0;
        for (int i = 0; i < nb; i++) { int v = bsums[i]; bsums[i] = run; run += v; }
    }
}

__global__ void scan3_kernel(int* out, const int* __restrict__ bsums, int n,
                             int total) {
    int i = blockIdx.x * blockDim.x + threadIdx.x;
    if (i < n) out[i] += bsums[i >> 10];
    if (i == 0) out[n] = total;
}

__global__ void fill_kernel(const int* __restrict__ src,
                            const int* __restrict__ dst,
                            const int* __restrict__ rowptr,
                            int* __restrict__ cursor, int* __restrict__ csrc,
                            int E) {
    int e = blockIdx.x * blockDim.x + threadIdx.x;
    if (e < E) {
        int d = dst[e];
        int pos = atomicAdd(&cursor[d], 1);
        csrc[rowptr[d] + pos] = src[e];
    }
}

// ---------------------------------------------------------------------------
// Host
// ---------------------------------------------------------------------------
static inline void* sym(const void* s) {
    void* p = nullptr;
    cudaGetSymbolAddress(&p, s);
    return p;
}

static void build_csr(const int* src, const int* dst, int Nd, int* rowptr,
                      int* csrc, int* cnt, int* bsums) {
    int nb = (Nd + 1023) / 1024;
    zero_kernel<<<(Nd + 255) / 256, 256>>>(cnt, Nd);
    count_kernel<<<(NE + 255) / 256, 256>>>(dst, cnt, NE);
    scan1_kernel<<<nb, 1024>>>(cnt, rowptr, bsums, Nd);
    scan2_kernel<<<1, 32>>>(bsums, nb);
    scan3_kernel<<<(Nd + 255) / 256, 256>>>(rowptr, bsums, Nd, NE);
    zero_kernel<<<(Nd + 255) / 256, 256>>>(cnt, Nd);
    fill_kernel<<<(NE + 255) / 256, 256>>>(src, dst, rowptr, cnt, csrc, NE);
}

extern "C" void kernel_launch(void* const* d_in, const int* in_sizes, int n_in,
                              void* d_out, int out_size) {
    const float* x_u   = (const float*)d_in[0];
    const float* x_v   = (const float*)d_in[1];
    const float* W_src = (const float*)d_in[2];
    const float* W_dst = (const float*)d_in[3];
    const float* att_s = (const float*)d_in[4];
    const float* att_d = (const float*)d_in[5];
    const float* bias  = (const float*)d_in[6];
    const float* lin_w = (const float*)d_in[7];
    const float* lin_b = (const float*)d_in[8];
    const int* ei_uv   = (const int*)d_in[9];
    const int* ei_vu   = (const int*)d_in[10];
    float* out = (float*)d_out;

    float* hs = (float*)sym(g_hs);
    bf16 *xu_hi = (bf16*)sym(g_xu_hi), *xu_lo = (bf16*)sym(g_xu_lo);
    bf16 *xv_hi = (bf16*)sym(g_xv_hi), *xv_lo = (bf16*)sym(g_xv_lo);
    bf16 *nv0_hi = (bf16*)sym(g_nv0_hi), *nv0_lo = (bf16*)sym(g_nv0_lo);
    bf16 *nu0_hi = (bf16*)sym(g_nu0_hi), *nu0_lo = (bf16*)sym(g_nu0_lo);
    bf16 *nu1_hi = (bf16*)sym(g_nu1_hi), *nu1_lo = (bf16*)sym(g_nu1_lo);
    float *es0 = (float*)sym(g_es0), *es1 = (float*)sym(g_es1), *es2 = (float*)sym(g_es2);
    float *ed0 = (float*)sym(g_ed0), *ed1 = (float*)sym(g_ed1), *ed2 = (float*)sym(g_ed2);
    float *cmbT_u = (float*)sym(g_cmbT_u), *cmbT_v = (float*)sym(g_cmbT_v);
    float *wsatt2T = (float*)sym(g_wsatt2T), *vd2T = (float*)sym(g_vd2T);
    bf16 *wt_hi = (bf16*)sym(g_wt_hi), *wt_lo = (bf16*)sym(g_wt_lo);
    bf16 *lt_hi = (bf16*)sym(g_lt_hi), *lt_lo = (bf16*)sym(g_lt_lo);
    int *rp_uv = (int*)sym(g_rowptr_uv), *rp_vu = (int*)sym(g_rowptr_vu);
    int *cs_uv = (int*)sym(g_csrc_uv), *cs_vu = (int*)sym(g_csrc_vu);
    int *cnt = (int*)sym(g_cnt), *bsums = (int*)sym(g_bsums);

    cudaFuncSetAttribute(mma_gemm_bf16<256, false>,
                         cudaFuncAttributeMaxDynamicSharedMemorySize, GSMEM);
    cudaFuncSetAttribute(mma_gemm_bf16<128, true>,
                         cudaFuncAttributeMaxDynamicSharedMemorySize, GSMEM);

    const size_t WSZ = 256 * 256, BSZ = 256;
    const int MT = (NU + 127) / 128;       // 391
    const dim3 g256(MT, 2), g128(MT, 1);
    const int XS4 = NU * 256 / 4;

    // 0: weight convert (single launch)
    wconv_all<<<896, 256>>>(W_src, lin_w, wt_hi, wt_lo, lt_hi, lt_lo);
    // 1,2: input splits
    xsplit_kernel<<<(XS4 + 255) / 256, 256>>>(x_u, xu_hi, xu_lo, XS4);
    xsplit_kernel<<<(XS4 + 255) / 256, 256>>>(x_v, xv_hi, xv_lo, XS4);
    // 3: gemm0 (placed early so ncu's capture window lands on it)
    mma_gemm_bf16<256, false><<<g256, 256, GSMEM>>>(
        xu_hi, xu_lo, wt_hi + 0 * WSZ, wt_lo + 0 * WSZ, nullptr, hs, NU);
    // 4: tiny attention matrices
    prep_smat_all<<<4, 256>>>(W_src, W_dst, att_s, att_d,
                              cmbT_u, cmbT_v, wsatt2T, vd2T);
    // 5,6: es/ed for layer 0 (both relations) in one pass per input
    smallmat_kernel<<<(NU + 7) / 8, 256>>>(x_u, cmbT_u, es0, ed1, NU);
    smallmat_kernel<<<(NV + 7) / 8, 256>>>(x_v, cmbT_v, es1, ed0, NV);
    // CSR
    build_csr(ei_uv, ei_uv + NE, NV, rp_uv, cs_uv, cnt, bsums);
    build_csr(ei_vu, ei_vu + NE, NU, rp_vu, cs_vu, cnt, bsums);

    // agg0: u->v  (+es2 for layer 2 from its output)
    agg_kernel<1><<<(NV + 7) / 8, 256>>>(hs, es0, ed0, rp_uv, cs_uv,
                                         bias + 0 * BSZ, nv0_hi, nv0_lo,
                                         wsatt2T, es2, NV);
    // gemm1: v->u
    mma_gemm_bf16<256, false><<<g256, 256, GSMEM>>>(
        xv_hi, xv_lo, wt_hi + 1 * WSZ, wt_lo + 1 * WSZ, nullptr, hs, NV);
    // agg1 (+ed2 for layer 2)
    agg_kernel<1><<<(NU + 7) / 8, 256>>>(hs, es1, ed1, rp_vu, cs_vu,
                                         bias + 1 * BSZ, nu0_hi, nu0_lo,
                                         vd2T, ed2, NU);
    // gemm2: layer-1 v->u on nv0
    mma_gemm_bf16<256, false><<<g256, 256, GSMEM>>>(
        nv0_hi, nv0_lo, wt_hi + 2 * WSZ, wt_lo + 2 * WSZ, nullptr, hs, NV);
    // agg2 -> nu1
    agg_kernel<0><<<(NU + 7) / 8, 256>>>(hs, es2, ed2, rp_vu, cs_vu,
                                         bias + 3 * BSZ, nu1_hi, nu1_lo,
                                         nullptr, nullptr, NU);
    // final linear
    mma_gemm_bf16<128, true><<<g128, 256, GSMEM>>>(
        nu1_hi, nu1_lo, lt_hi, lt_lo, lin_b, out, NU);
}